// round 10
// baseline (speedup 1.0000x reference)
#include <cuda_runtime.h>
#include <cuda_bf16.h>
#include <cstdint>
#include <cstddef>

// Problem constants
#define S_LEN   2048
#define BATCH   2
#define DIM     512
#define NHEAD   8
#define EDIM    512
#define HE_DIM  (NHEAD * EDIM)

#define TM 128
#define KC 32                         // bf16 elems per k-chunk (64B rows, SW64)
#define AB 8192                       // A tile bytes (hi or lo): 128*32*2

// ---------------------------------------------------------------------------
// Scratch (device globals — no allocation allowed)
// ---------------------------------------------------------------------------
__device__ __align__(16) __nv_bfloat16 g_xh[3][BATCH * S_LEN * DIM];
__device__ __align__(16) __nv_bfloat16 g_xl[3][BATCH * S_LEN * DIM];
__device__ __align__(16) __nv_bfloat16 g_wth[3][NHEAD * EDIM * DIM];  // W^T per head
__device__ __align__(16) __nv_bfloat16 g_wtl[3][NHEAD * EDIM * DIM];
__device__ __align__(16) __nv_bfloat16 g_woth[EDIM * HE_DIM];
__device__ __align__(16) __nv_bfloat16 g_wotl[EDIM * HE_DIM];
__device__ __align__(16) __nv_bfloat16 g_qh[BATCH * NHEAD * S_LEN * EDIM];
__device__ __align__(16) __nv_bfloat16 g_ql[BATCH * NHEAD * S_LEN * EDIM];
__device__ __align__(16) __nv_bfloat16 g_kh[BATCH * NHEAD * S_LEN * EDIM];
__device__ __align__(16) __nv_bfloat16 g_kl[BATCH * NHEAD * S_LEN * EDIM];
__device__ __align__(16) __nv_bfloat16 g_vth[BATCH * NHEAD * EDIM * S_LEN]; // v^T [e,s]
__device__ __align__(16) __nv_bfloat16 g_vtl[BATCH * NHEAD * EDIM * S_LEN];
__device__ __align__(16) float g_attn[(size_t)BATCH * NHEAD * S_LEN * S_LEN];
__device__ __align__(16) __nv_bfloat16 g_ah[(size_t)BATCH * NHEAD * S_LEN * S_LEN];
__device__ __align__(16) __nv_bfloat16 g_al[(size_t)BATCH * NHEAD * S_LEN * S_LEN];
__device__ __align__(16) __nv_bfloat16 g_cath[BATCH * S_LEN * HE_DIM];
__device__ __align__(16) __nv_bfloat16 g_catl[BATCH * S_LEN * HE_DIM];
__device__ int g_mask_kind;

// ---------------------------------------------------------------------------
// PTX helpers (base sm_103 ISA only: cp.async, ldmatrix, mma.sync)
// ---------------------------------------------------------------------------
__device__ __forceinline__ uint32_t smem_u32(const void* p) {
    uint32_t a;
    asm("{ .reg .u64 t; cvta.to.shared.u64 t, %1; cvt.u32.u64 %0, t; }" : "=r"(a) : "l"(p));
    return a;
}
// 64B-row swizzle (Swizzle<2,4,3>): XOR bits [4:6) with bits [7:9)
#define SW64(off) ((off) ^ (((off) >> 3) & 0x30))

#define CP16(sa, gp) asm volatile( \
    "cp.async.cg.shared.global [%0], [%1], 16;" :: "r"(sa), "l"(gp) : "memory")
#define CP_COMMIT() asm volatile("cp.async.commit_group;" ::: "memory")
#define CP_WAIT1() asm volatile("cp.async.wait_group 1;" ::: "memory")
#define CP_WAIT0() asm volatile("cp.async.wait_group 0;" ::: "memory")

#define LDSM4(r, a) asm volatile( \
    "ldmatrix.sync.aligned.m8n8.x4.shared.b16 {%0,%1,%2,%3}, [%4];" \
    : "=r"((r)[0]), "=r"((r)[1]), "=r"((r)[2]), "=r"((r)[3]) : "r"(a))

#define MMA16816(d, a, b0, b1) asm volatile( \
    "mma.sync.aligned.m16n8k16.row.col.f32.bf16.bf16.f32 " \
    "{%0,%1,%2,%3}, {%4,%5,%6,%7}, {%8,%9}, {%0,%1,%2,%3};" \
    : "+f"((d)[0]), "+f"((d)[1]), "+f"((d)[2]), "+f"((d)[3]) \
    : "r"((a)[0]), "r"((a)[1]), "r"((a)[2]), "r"((a)[3]), "r"(b0), "r"(b1))

__device__ __forceinline__ void split2(float v, __nv_bfloat16& h, __nv_bfloat16& l) {
    h = __float2bfloat16(v);
    l = __float2bfloat16(v - __bfloat162float(h));
}

// ---------------------------------------------------------------------------
// Mask dtype detection (bool may arrive as u8 / i32 / f32)
// ---------------------------------------------------------------------------
__global__ void detect_mask_kind(const void* __restrict__ mask) {
    const unsigned int* w = (const unsigned int*)mask;
    bool all01 = true, allf = true;
    for (int i = 0; i < 256; i++) {
        unsigned int x = w[i];
        if (x > 1u) all01 = false;
        if (x != 0u && x != 0x3F800000u) allf = false;
    }
    g_mask_kind = all01 ? 1 : (allf ? 2 : 0);
}

// ---------------------------------------------------------------------------
// Split fp32 -> (hi, lo) bf16, flat
// ---------------------------------------------------------------------------
__global__ void split_flat(const float* __restrict__ src,
                           __nv_bfloat16* __restrict__ hi,
                           __nv_bfloat16* __restrict__ lo, int n) {
    int i = blockIdx.x * blockDim.x + threadIdx.x;
    if (i < n) {
        __nv_bfloat16 h, l;
        split2(src[i], h, l);
        hi[i] = h;
        lo[i] = l;
    }
}

// ---------------------------------------------------------------------------
// Split + transpose: src [Z][R][C] fp32 -> dst [Z][C][R] bf16 hi/lo
// ---------------------------------------------------------------------------
__global__ void split_T(const float* __restrict__ src,
                        __nv_bfloat16* __restrict__ hi,
                        __nv_bfloat16* __restrict__ lo, int R, int C) {
    __shared__ float tile[32][33];
    const int z = blockIdx.z;
    const float* s = src + (size_t)z * R * C;
    __nv_bfloat16* dh = hi + (size_t)z * R * C;
    __nv_bfloat16* dl = lo + (size_t)z * R * C;
    const int c0 = blockIdx.x * 32, r0 = blockIdx.y * 32;
    const int tx = threadIdx.x, ty = threadIdx.y;
#pragma unroll
    for (int i = 0; i < 4; i++)
        tile[ty + i * 8][tx] = s[(size_t)(r0 + ty + i * 8) * C + c0 + tx];
    __syncthreads();
#pragma unroll
    for (int i = 0; i < 4; i++) {
        __nv_bfloat16 h, l;
        split2(tile[tx][ty + i * 8], h, l);
        const size_t idx = (size_t)(c0 + ty + i * 8) * R + r0 + tx;
        dh[idx] = h;
        dl[idx] = l;
    }
}

// ---------------------------------------------------------------------------
// bf16x3 HMMA GEMM: C = A @ B^T (+bias). Both operands K-major as (hi,lo).
// CTA tile 128 x WN, K-chunk 32, 3-stage cp.async pipeline.
//   WN=128: warp m64n32, 2 CTAs/SM (96KB smem)  — for small-N GEMMs
//   WN=256: warp m64n64, 1 CTA/SM (144KB smem)  — 31% less smem traffic/FLOP
// 8 warps: warpM = wid&1, warpN = wid>>1 (each covers WN/4 cols).
// OM: 0 = fp32 out, 1 = split-bf16 out, 2 = split-bf16 transposed out.
// ---------------------------------------------------------------------------
template <int OM, int WN>
__global__ __launch_bounds__(256, WN == 128 ? 2 : 1)
void mm_hmma(const __nv_bfloat16* __restrict__ Ah, const __nv_bfloat16* __restrict__ Al,
             long aBatch, int aDiv, int lda,
             const __nv_bfloat16* __restrict__ Bh, const __nv_bfloat16* __restrict__ Bl,
             long bBatch, int bMod, int ldb,
             const float* __restrict__ biasAll, int biasMode,
             void* __restrict__ C0, __nv_bfloat16* __restrict__ Cl,
             long cBatch, int cMode, int ldc, int K) {
    constexpr int NT = WN / 32;        // n8-tiles per warp
    constexpr int PB = WN / 64;        // B LDSM4 frags per warp per term
    constexpr int BB = WN * 64;        // B tile bytes (hi or lo)
    constexpr int STG = 2 * AB + 2 * BB;
    constexpr int WCOL = WN / 4;       // warp n-extent

    extern __shared__ char smem[];
    const uint32_t sb = smem_u32(smem);
    const int t = threadIdx.x;
    const int lane = t & 31;
    const int wid = t >> 5;
    const int warpM = wid & 1;
    const int warpN = wid >> 1;
    const int z = blockIdx.z;
    const int row0 = blockIdx.y * TM;
    const int col0 = blockIdx.x * WN;

    const __nv_bfloat16* pAh = Ah + (size_t)(z / aDiv) * (size_t)aBatch;
    const __nv_bfloat16* pAl = Al + (size_t)(z / aDiv) * (size_t)aBatch;
    const __nv_bfloat16* pBh = Bh + (size_t)(z % bMod) * (size_t)bBatch;
    const __nv_bfloat16* pBl = Bl + (size_t)(z % bMod) * (size_t)bBatch;

    float acc[4][NT][4] = {};

    auto issue = [&](int c) {
        const int k0 = c * KC;
        const uint32_t s0 = sb + (c % 3) * STG;
#pragma unroll
        for (int i = 0; i < 2; i++) {
            const int ch = t + i * 256;
            const int r = ch >> 2;                // 0..127
            const int q = (ch & 3) * 8;
            const uint32_t so = SW64((uint32_t)(r * 64 + q * 2));
            const size_t ao = (size_t)(row0 + r) * lda + k0 + q;
            CP16(s0 + so, pAh + ao);
            CP16(s0 + AB + so, pAl + ao);
        }
#pragma unroll
        for (int i = 0; i < BB / 4096; i++) {
            const int ch = t + i * 256;
            const int r = ch >> 2;                // 0..WN-1
            const int q = (ch & 3) * 8;
            const uint32_t so = SW64((uint32_t)(r * 64 + q * 2));
            const size_t bo = (size_t)(col0 + r) * ldb + k0 + q;
            CP16(s0 + 2 * AB + so, pBh + bo);
            CP16(s0 + 2 * AB + BB + so, pBl + bo);
        }
    };

    const int arow = lane & 15;
    const int koff = (lane >> 4) * 16;            // byte offset of k half

    auto compute = [&](int c) {
        const uint32_t s0 = sb + (c % 3) * STG;
#pragma unroll
        for (int ks = 0; ks < 2; ks++) {
            uint32_t fah[4][4], fx[4][4], fb[PB][4];
#pragma unroll
            for (int p = 0; p < PB; p++) {
                const uint32_t off = SW64(
                    (uint32_t)((warpN * WCOL + p * 16 + arow) * 64 + ks * 32 + koff));
                LDSM4(fb[p], s0 + 2 * AB + off);  // Bh
            }
#pragma unroll
            for (int mt = 0; mt < 4; mt++) {
                const uint32_t off = SW64(
                    (uint32_t)((warpM * 64 + mt * 16 + arow) * 64 + ks * 32 + koff));
                LDSM4(fah[mt], s0 + off);         // Ah
            }
#pragma unroll
            for (int mt = 0; mt < 4; mt++)
#pragma unroll
                for (int nt = 0; nt < NT; nt++)
                    MMA16816(acc[mt][nt], fah[mt], fb[nt >> 1][nt & 1], fb[nt >> 1][(nt & 1) + 2]);
#pragma unroll
            for (int mt = 0; mt < 4; mt++) {
                const uint32_t off = SW64(
                    (uint32_t)((warpM * 64 + mt * 16 + arow) * 64 + ks * 32 + koff));
                LDSM4(fx[mt], s0 + AB + off);     // Al
            }
#pragma unroll
            for (int mt = 0; mt < 4; mt++)
#pragma unroll
                for (int nt = 0; nt < NT; nt++)
                    MMA16816(acc[mt][nt], fx[mt], fb[nt >> 1][nt & 1], fb[nt >> 1][(nt & 1) + 2]);
#pragma unroll
            for (int p = 0; p < PB; p++) {
                const uint32_t off = SW64(
                    (uint32_t)((warpN * WCOL + p * 16 + arow) * 64 + ks * 32 + koff));
                LDSM4(fb[p], s0 + 2 * AB + BB + off);  // Bl (reuse fb regs)
            }
#pragma unroll
            for (int mt = 0; mt < 4; mt++)
#pragma unroll
                for (int nt = 0; nt < NT; nt++)
                    MMA16816(acc[mt][nt], fah[mt], fb[nt >> 1][nt & 1], fb[nt >> 1][(nt & 1) + 2]);
        }
    };

    const int NC = K / KC;
    issue(0);
    CP_COMMIT();
    issue(1);
    CP_COMMIT();
    for (int c = 0; c < NC; c++) {
        if (c + 1 < NC) CP_WAIT1(); else CP_WAIT0();
        __syncthreads();                  // chunk c visible; fences compute(c-1)
        compute(c);
        if (c + 2 < NC) {
            issue(c + 2);
            CP_COMMIT();
        }
    }
    __syncthreads();                      // all compute done before smem reuse

    // ---------------- Epilogue: accum -> smem -> global, 128 cols at a time --
    size_t zoff;
    if (cMode == 0) zoff = (size_t)z * (size_t)cBatch;
    else zoff = (size_t)(z / NHEAD) * S_LEN * HE_DIM + (size_t)(z % NHEAD) * EDIM;
    const float* bias = nullptr;
    if (biasMode == 1) bias = biasAll + (size_t)(z % NHEAD) * EDIM;
    else if (biasMode == 2) bias = biasAll;

    float* esm = (float*)smem;                    // [128][132]
    constexpr int NB = WN / 128;
#pragma unroll
    for (int nb = 0; nb < NB; nb++) {
        if ((warpN * WCOL) / 128 == nb) {         // warp's 64/32-col range is in this block
#pragma unroll
            for (int mt = 0; mt < 4; mt++)
#pragma unroll
                for (int nt = 0; nt < NT; nt++) {
                    const int r = warpM * 64 + mt * 16 + (lane >> 2);
                    const int cc = warpN * WCOL + nt * 8 - nb * 128 + (lane & 3) * 2;
                    *(float2*)&esm[r * 132 + cc] = make_float2(acc[mt][nt][0], acc[mt][nt][1]);
                    *(float2*)&esm[(r + 8) * 132 + cc] = make_float2(acc[mt][nt][2], acc[mt][nt][3]);
                }
        }
        __syncthreads();
        const int colB = col0 + nb * 128;

        if (OM != 2) {
            const int m = t >> 1, cs = (t & 1) * 64;
#pragma unroll
            for (int jj = 0; jj < 64; jj += 16) {
                float v[16];
#pragma unroll
                for (int j = 0; j < 16; j++) {
                    v[j] = esm[m * 132 + cs + jj + j];
                    if (biasMode) v[j] += bias[colB + cs + jj + j];
                }
                const size_t idx = zoff + (size_t)(row0 + m) * ldc + colB + cs + jj;
                if (OM == 0) {
                    float4* dst = (float4*)((float*)C0 + idx);
#pragma unroll
                    for (int j = 0; j < 4; j++)
                        dst[j] = make_float4(v[4 * j], v[4 * j + 1], v[4 * j + 2], v[4 * j + 3]);
                } else {
                    __align__(16) __nv_bfloat16 hb[16], lb[16];
#pragma unroll
                    for (int j = 0; j < 16; j++) split2(v[j], hb[j], lb[j]);
                    *(uint4*)((__nv_bfloat16*)C0 + idx) = *(uint4*)hb;
                    *(uint4*)((__nv_bfloat16*)C0 + idx + 8) = *(uint4*)(hb + 8);
                    *(uint4*)(Cl + idx) = *(uint4*)lb;
                    *(uint4*)(Cl + idx + 8) = *(uint4*)(lb + 8);
                }
            }
        } else {
            const int e = t >> 1, m0 = (t & 1) * 64;
            const float bv = biasMode ? bias[colB + e] : 0.0f;
#pragma unroll
            for (int jj = 0; jj < 64; jj += 16) {
                __align__(16) __nv_bfloat16 hb[16], lb[16];
#pragma unroll
                for (int j = 0; j < 16; j++)
                    split2(esm[(m0 + jj + j) * 132 + e] + bv, hb[j], lb[j]);
                const size_t idx = zoff + (size_t)(colB + e) * ldc + row0 + m0 + jj;
                *(uint4*)((__nv_bfloat16*)C0 + idx) = *(uint4*)hb;
                *(uint4*)((__nv_bfloat16*)C0 + idx + 8) = *(uint4*)(hb + 8);
                *(uint4*)(Cl + idx) = *(uint4*)lb;
                *(uint4*)(Cl + idx + 8) = *(uint4*)(lb + 8);
            }
        }
        __syncthreads();
    }
}

// ---------------------------------------------------------------------------
// Masked softmax: reads fp32 g_attn row, writes split bf16 to g_ah/g_al.
// ---------------------------------------------------------------------------
__global__ void masked_softmax_split(const void* __restrict__ mask) {
    const int z = blockIdx.x;
    const int b = z / (NHEAD * S_LEN);
    const int s = z % S_LEN;
    const float* row = g_attn + (size_t)z * S_LEN;
    __nv_bfloat16* oh = g_ah + (size_t)z * S_LEN;
    __nv_bfloat16* ol = g_al + (size_t)z * S_LEN;
    const size_t mbase = (size_t)b * S_LEN * S_LEN + (size_t)s * S_LEN;
    const int kind = g_mask_kind;
    const int tid = threadIdx.x;

    float v[8];
    float mx = -3.0e38f;
#pragma unroll
    for (int i = 0; i < 8; i++) {
        const int tt = tid + i * 256;
        bool mk;
        if (kind == 1)      mk = ((const int*)mask)[mbase + tt] != 0;
        else if (kind == 2) mk = ((const float*)mask)[mbase + tt] != 0.0f;
        else                mk = ((const unsigned char*)mask)[mbase + tt] != 0;
        const float x = mk ? row[tt] : -1.0e9f;
        v[i] = x;
        mx = fmaxf(mx, x);
    }
    __shared__ float sm[256];
    sm[tid] = mx;
    __syncthreads();
    for (int o = 128; o > 0; o >>= 1) {
        if (tid < o) sm[tid] = fmaxf(sm[tid], sm[tid + o]);
        __syncthreads();
    }
    mx = sm[0];
    __syncthreads();
    float sum = 0.0f;
#pragma unroll
    for (int i = 0; i < 8; i++) {
        v[i] = __expf(v[i] - mx);
        sum += v[i];
    }
    sm[tid] = sum;
    __syncthreads();
    for (int o = 128; o > 0; o >>= 1) {
        if (tid < o) sm[tid] += sm[tid + o];
        __syncthreads();
    }
    const float inv = 1.0f / sm[0];
#pragma unroll
    for (int i = 0; i < 8; i++) {
        __nv_bfloat16 h, l;
        split2(v[i] * inv, h, l);
        oh[tid + i * 256] = h;
        ol[tid + i * 256] = l;
    }
}

// ---------------------------------------------------------------------------
// Launcher
// ---------------------------------------------------------------------------
static void* sym(const void* s) {
    void* p = nullptr;
    cudaGetSymbolAddress(&p, s);
    return p;
}

extern "C" void kernel_launch(void* const* d_in, const int* in_sizes, int n_in,
                              void* d_out, int out_size) {
    (void)in_sizes; (void)n_in; (void)out_size;

    const float* query = (const float*)d_in[0];
    const float* key   = (const float*)d_in[1];
    const float* value = (const float*)d_in[2];
    const void*  mask  = d_in[3];
    const float* Wq = (const float*)d_in[4];
    const float* bq = (const float*)d_in[5];
    const float* Wk = (const float*)d_in[6];
    const float* bk = (const float*)d_in[7];
    const float* Wv = (const float*)d_in[8];
    const float* bv = (const float*)d_in[9];
    const float* Wo = (const float*)d_in[10];
    const float* bo = (const float*)d_in[11];
    float* out = (float*)d_out;

    typedef __nv_bfloat16 bf;
    bf* xh0 = (bf*)sym(g_xh);                       bf* xl0 = (bf*)sym(g_xl);
    bf* xh1 = xh0 + (size_t)BATCH * S_LEN * DIM;    bf* xl1 = xl0 + (size_t)BATCH * S_LEN * DIM;
    bf* xh2 = xh1 + (size_t)BATCH * S_LEN * DIM;    bf* xl2 = xl1 + (size_t)BATCH * S_LEN * DIM;
    bf* wth0 = (bf*)sym(g_wth);                     bf* wtl0 = (bf*)sym(g_wtl);
    bf* wth1 = wth0 + (size_t)NHEAD * EDIM * DIM;   bf* wtl1 = wtl0 + (size_t)NHEAD * EDIM * DIM;
    bf* wth2 = wth1 + (size_t)NHEAD * EDIM * DIM;   bf* wtl2 = wtl1 + (size_t)NHEAD * EDIM * DIM;
    bf* woth = (bf*)sym(g_woth);  bf* wotl = (bf*)sym(g_wotl);
    bf* qh = (bf*)sym(g_qh);      bf* ql = (bf*)sym(g_ql);
    bf* kh = (bf*)sym(g_kh);      bf* kl = (bf*)sym(g_kl);
    bf* vth = (bf*)sym(g_vth);    bf* vtl = (bf*)sym(g_vtl);
    float* attn = (float*)sym(g_attn);
    bf* ah = (bf*)sym(g_ah);      bf* al = (bf*)sym(g_al);
    bf* cath = (bf*)sym(g_cath);  bf* catl = (bf*)sym(g_catl);

    const int SM128 = 3 * (2 * AB + 2 * 128 * 64);   // 98304
    const int SM256 = 3 * (2 * AB + 2 * 256 * 64);   // 147456
    cudaFuncSetAttribute(mm_hmma<0, 128>, cudaFuncAttributeMaxDynamicSharedMemorySize, SM128);
    cudaFuncSetAttribute(mm_hmma<0, 256>, cudaFuncAttributeMaxDynamicSharedMemorySize, SM256);
    cudaFuncSetAttribute(mm_hmma<1, 256>, cudaFuncAttributeMaxDynamicSharedMemorySize, SM256);
    cudaFuncSetAttribute(mm_hmma<2, 256>, cudaFuncAttributeMaxDynamicSharedMemorySize, SM256);

    const int BIG = 1 << 30;

    detect_mask_kind<<<1, 1>>>(mask);

    // --- input / weight split(+transpose) prep ---
    const int nX = BATCH * S_LEN * DIM;
    split_flat<<<(nX + 255) / 256, 256>>>(query, xh0, xl0, nX);
    split_flat<<<(nX + 255) / 256, 256>>>(key,   xh1, xl1, nX);
    split_flat<<<(nX + 255) / 256, 256>>>(value, xh2, xl2, nX);
    {
        dim3 g(EDIM / 32, DIM / 32, NHEAD), bdim(32, 8);
        split_T<<<g, bdim>>>(Wq, wth0, wtl0, DIM, EDIM);
        split_T<<<g, bdim>>>(Wk, wth1, wtl1, DIM, EDIM);
        split_T<<<g, bdim>>>(Wv, wth2, wtl2, DIM, EDIM);
    }
    {
        dim3 g(EDIM / 32, HE_DIM / 32, 1), bdim(32, 8);
        split_T<<<g, bdim>>>(Wo, woth, wotl, HE_DIM, EDIM);
    }

    // --- projections: X[s,d] @ W^T[e,d]^T -> [b,h,s,e] (v transposed) ---
    {
        dim3 grid(EDIM / 256, S_LEN / TM, BATCH * NHEAD);
        mm_hmma<1, 256><<<grid, 256, SM256>>>(
            xh0, xl0, (long)S_LEN * DIM, NHEAD, DIM,
            wth0, wtl0, (long)EDIM * DIM, NHEAD, DIM,
            bq, 1, qh, ql, (long)S_LEN * EDIM, 0, EDIM, DIM);
        mm_hmma<1, 256><<<grid, 256, SM256>>>(
            xh1, xl1, (long)S_LEN * DIM, NHEAD, DIM,
            wth1, wtl1, (long)EDIM * DIM, NHEAD, DIM,
            bk, 1, kh, kl, (long)S_LEN * EDIM, 0, EDIM, DIM);
        mm_hmma<2, 256><<<grid, 256, SM256>>>(
            xh2, xl2, (long)S_LEN * DIM, NHEAD, DIM,
            wth2, wtl2, (long)EDIM * DIM, NHEAD, DIM,
            bv, 1, vth, vtl, (long)EDIM * S_LEN, 0, S_LEN, DIM);
    }

    // --- scores: q[s,e] @ k[t,e]^T -> fp32 attn ---
    {
        dim3 grid(S_LEN / 256, S_LEN / TM, BATCH * NHEAD);
        mm_hmma<0, 256><<<grid, 256, SM256>>>(
            qh, ql, (long)S_LEN * EDIM, 1, EDIM,
            kh, kl, (long)S_LEN * EDIM, BIG, EDIM,
            nullptr, 0, attn, nullptr, (long)S_LEN * S_LEN, 0, S_LEN, EDIM);
    }

    // --- masked softmax -> split bf16 ---
    masked_softmax_split<<<BATCH * NHEAD * S_LEN, 256>>>(mask);

    // --- PV: attn[s,t] @ vT[e,t]^T -> cat[b,s,h*E+e] ---
    {
        dim3 grid(EDIM / 256, S_LEN / TM, BATCH * NHEAD);
        mm_hmma<1, 256><<<grid, 256, SM256>>>(
            ah, al, (long)S_LEN * S_LEN, 1, S_LEN,
            vth, vtl, (long)EDIM * S_LEN, BIG, S_LEN,
            nullptr, 0, cath, catl, 0L, 1, HE_DIM, S_LEN);
    }

    // --- output projection (small N -> keep 128-wide occ-2 variant) ---
    {
        dim3 grid(EDIM / 128, (BATCH * S_LEN) / TM, 1);
        mm_hmma<0, 128><<<grid, 256, SM128>>>(
            cath, catl, 0L, 1, HE_DIM,
            woth, wotl, 0L, 1, HE_DIM,
            bo, 2, out, nullptr, 0L, 0, EDIM, HE_DIM);
    }
}

// round 11
// speedup vs baseline: 1.1702x; 1.1702x over previous
#include <cuda_runtime.h>
#include <cuda_bf16.h>
#include <cstdint>
#include <cstddef>

// Problem constants
#define S_LEN   2048
#define BATCH   2
#define DIM     512
#define NHEAD   8
#define EDIM    512
#define HE_DIM  (NHEAD * EDIM)

// GEMM tile config: CTA 128x128, 4 warps of m64n64, K-chunk 32 (64B rows, SW64)
#define TM 128
#define KC 32
#define AB 8192                       // one operand tile (hi or lo): 128*32*2
#define STG (4 * AB)                  // Ah, Al, Bh, Bl = 32768
#define SMEM_DYN (3 * STG)            // 98304 -> 2 CTAs/SM

// ---------------------------------------------------------------------------
// Scratch (device globals — no allocation allowed)
// ---------------------------------------------------------------------------
__device__ __align__(16) __nv_bfloat16 g_xh[3][BATCH * S_LEN * DIM];
__device__ __align__(16) __nv_bfloat16 g_xl[3][BATCH * S_LEN * DIM];
__device__ __align__(16) __nv_bfloat16 g_wth[3][NHEAD * EDIM * DIM];  // W^T per head
__device__ __align__(16) __nv_bfloat16 g_wtl[3][NHEAD * EDIM * DIM];
__device__ __align__(16) __nv_bfloat16 g_woth[EDIM * HE_DIM];
__device__ __align__(16) __nv_bfloat16 g_wotl[EDIM * HE_DIM];
__device__ __align__(16) __nv_bfloat16 g_qh[BATCH * NHEAD * S_LEN * EDIM];
__device__ __align__(16) __nv_bfloat16 g_ql[BATCH * NHEAD * S_LEN * EDIM];
__device__ __align__(16) __nv_bfloat16 g_kh[BATCH * NHEAD * S_LEN * EDIM];
__device__ __align__(16) __nv_bfloat16 g_kl[BATCH * NHEAD * S_LEN * EDIM];
__device__ __align__(16) __nv_bfloat16 g_vth[BATCH * NHEAD * EDIM * S_LEN]; // v^T [e,s]
__device__ __align__(16) __nv_bfloat16 g_vtl[BATCH * NHEAD * EDIM * S_LEN];
__device__ __align__(16) float g_attn[(size_t)BATCH * NHEAD * S_LEN * S_LEN];
__device__ __align__(16) __nv_bfloat16 g_ah[(size_t)BATCH * NHEAD * S_LEN * S_LEN];
__device__ __align__(16) __nv_bfloat16 g_al[(size_t)BATCH * NHEAD * S_LEN * S_LEN];
__device__ __align__(16) __nv_bfloat16 g_cath[BATCH * S_LEN * HE_DIM];
__device__ __align__(16) __nv_bfloat16 g_catl[BATCH * S_LEN * HE_DIM];
__device__ int g_mask_kind;

// ---------------------------------------------------------------------------
// PTX helpers (base sm_103 ISA only: cp.async, ldmatrix, mma.sync)
// ---------------------------------------------------------------------------
__device__ __forceinline__ uint32_t smem_u32(const void* p) {
    uint32_t a;
    asm("{ .reg .u64 t; cvta.to.shared.u64 t, %1; cvt.u32.u64 %0, t; }" : "=r"(a) : "l"(p));
    return a;
}
// 64B-row swizzle (Swizzle<2,4,3>): XOR bits [4:6) with bits [7:9)
#define SW64(off) ((off) ^ (((off) >> 3) & 0x30))

#define CP16(sa, gp) asm volatile( \
    "cp.async.cg.shared.global [%0], [%1], 16;" :: "r"(sa), "l"(gp) : "memory")
#define CP_COMMIT() asm volatile("cp.async.commit_group;" ::: "memory")
#define CP_WAIT1() asm volatile("cp.async.wait_group 1;" ::: "memory")
#define CP_WAIT0() asm volatile("cp.async.wait_group 0;" ::: "memory")

#define LDSM4(r, a) asm volatile( \
    "ldmatrix.sync.aligned.m8n8.x4.shared.b16 {%0,%1,%2,%3}, [%4];" \
    : "=r"((r)[0]), "=r"((r)[1]), "=r"((r)[2]), "=r"((r)[3]) : "r"(a))

#define MMA16816(d, a, b0, b1) asm volatile( \
    "mma.sync.aligned.m16n8k16.row.col.f32.bf16.bf16.f32 " \
    "{%0,%1,%2,%3}, {%4,%5,%6,%7}, {%8,%9}, {%0,%1,%2,%3};" \
    : "+f"((d)[0]), "+f"((d)[1]), "+f"((d)[2]), "+f"((d)[3]) \
    : "r"((a)[0]), "r"((a)[1]), "r"((a)[2]), "r"((a)[3]), "r"(b0), "r"(b1))

__device__ __forceinline__ void split2(float v, __nv_bfloat16& h, __nv_bfloat16& l) {
    h = __float2bfloat16(v);
    l = __float2bfloat16(v - __bfloat162float(h));
}

// ---------------------------------------------------------------------------
// Mask dtype detection (bool may arrive as u8 / i32 / f32)
// ---------------------------------------------------------------------------
__global__ void detect_mask_kind(const void* __restrict__ mask) {
    const unsigned int* w = (const unsigned int*)mask;
    bool all01 = true, allf = true;
    for (int i = 0; i < 256; i++) {
        unsigned int x = w[i];
        if (x > 1u) all01 = false;
        if (x != 0u && x != 0x3F800000u) allf = false;
    }
    g_mask_kind = all01 ? 1 : (allf ? 2 : 0);
}

// ---------------------------------------------------------------------------
// Split fp32 -> (hi, lo) bf16, flat
// ---------------------------------------------------------------------------
__global__ void split_flat(const float* __restrict__ src,
                           __nv_bfloat16* __restrict__ hi,
                           __nv_bfloat16* __restrict__ lo, int n) {
    int i = blockIdx.x * blockDim.x + threadIdx.x;
    if (i < n) {
        __nv_bfloat16 h, l;
        split2(src[i], h, l);
        hi[i] = h;
        lo[i] = l;
    }
}

// ---------------------------------------------------------------------------
// Split + transpose: src [Z][R][C] fp32 -> dst [Z][C][R] bf16 hi/lo
// ---------------------------------------------------------------------------
__global__ void split_T(const float* __restrict__ src,
                        __nv_bfloat16* __restrict__ hi,
                        __nv_bfloat16* __restrict__ lo, int R, int C) {
    __shared__ float tile[32][33];
    const int z = blockIdx.z;
    const float* s = src + (size_t)z * R * C;
    __nv_bfloat16* dh = hi + (size_t)z * R * C;
    __nv_bfloat16* dl = lo + (size_t)z * R * C;
    const int c0 = blockIdx.x * 32, r0 = blockIdx.y * 32;
    const int tx = threadIdx.x, ty = threadIdx.y;
#pragma unroll
    for (int i = 0; i < 4; i++)
        tile[ty + i * 8][tx] = s[(size_t)(r0 + ty + i * 8) * C + c0 + tx];
    __syncthreads();
#pragma unroll
    for (int i = 0; i < 4; i++) {
        __nv_bfloat16 h, l;
        split2(tile[tx][ty + i * 8], h, l);
        const size_t idx = (size_t)(c0 + ty + i * 8) * R + r0 + tx;
        dh[idx] = h;
        dl[idx] = l;
    }
}

// ---------------------------------------------------------------------------
// bf16x3 HMMA GEMM: C = A @ B^T (+bias). Both operands K-major as (hi,lo).
// CTA 128x128, K-chunk 32, 3-stage cp.async pipeline, 2 CTAs/SM.
// 4 warps (128 thr), each m64 x n64: warpM = wid&1, warpN = wid>>1.
// Per-chunk smem reads: 64KB (vs 96KB @ m64n32) — 25% less total port traffic.
// OM: 0 = fp32 out, 1 = split-bf16 out, 2 = split-bf16 transposed out.
// ---------------------------------------------------------------------------
template <int OM>
__global__ __launch_bounds__(128, 2)
void mm_hmma(const __nv_bfloat16* __restrict__ Ah, const __nv_bfloat16* __restrict__ Al,
             long aBatch, int aDiv, int lda,
             const __nv_bfloat16* __restrict__ Bh, const __nv_bfloat16* __restrict__ Bl,
             long bBatch, int bMod, int ldb,
             const float* __restrict__ biasAll, int biasMode,
             void* __restrict__ C0, __nv_bfloat16* __restrict__ Cl,
             long cBatch, int cMode, int ldc, int K) {
    extern __shared__ char smem[];
    const uint32_t sb = smem_u32(smem);
    const int t = threadIdx.x;
    const int lane = t & 31;
    const int wid = t >> 5;               // 0..3
    const int warpM = wid & 1;
    const int warpN = wid >> 1;
    const int z = blockIdx.z;
    const int row0 = blockIdx.y * TM;
    const int col0 = blockIdx.x * 128;

    const __nv_bfloat16* pAh = Ah + (size_t)(z / aDiv) * (size_t)aBatch;
    const __nv_bfloat16* pAl = Al + (size_t)(z / aDiv) * (size_t)aBatch;
    const __nv_bfloat16* pBh = Bh + (size_t)(z % bMod) * (size_t)bBatch;
    const __nv_bfloat16* pBl = Bl + (size_t)(z % bMod) * (size_t)bBatch;

    float acc[4][8][4] = {};              // m4-tiles x n8-tiles x frag

    auto issue = [&](int c) {
        const int k0 = c * KC;
        const uint32_t s0 = sb + (c % 3) * STG;
#pragma unroll
        for (int i = 0; i < 4; i++) {
            const int ch = t + i * 128;   // 512 16B chunks per tile
            const int r = ch >> 2;        // 0..127
            const int q = (ch & 3) * 8;
            const uint32_t so = SW64((uint32_t)(r * 64 + q * 2));
            const size_t ao = (size_t)(row0 + r) * lda + k0 + q;
            const size_t bo = (size_t)(col0 + r) * ldb + k0 + q;
            CP16(s0 + so, pAh + ao);
            CP16(s0 + AB + so, pAl + ao);
            CP16(s0 + 2 * AB + so, pBh + bo);
            CP16(s0 + 3 * AB + so, pBl + bo);
        }
    };

    const int arow = lane & 15;
    const int koff = (lane >> 4) * 16;    // byte offset of k half

    auto compute = [&](int c) {
        const uint32_t s0 = sb + (c % 3) * STG;
#pragma unroll
        for (int ks = 0; ks < 2; ks++) {
            // Term order hh -> lh -> hl with register reuse (peak 48 frag regs):
            // load Ah,Bh -> hh; load Al -> lh; overwrite Al-slot... (Ah kept), Bl over Bh -> hl
            uint32_t fa[4][4], f2[4][4], fb[4][4];
            uint32_t aoffs[4], boffs[4];
#pragma unroll
            for (int i = 0; i < 4; i++) {
                aoffs[i] = SW64((uint32_t)((warpM * 64 + i * 16 + arow) * 64 + ks * 32 + koff));
                boffs[i] = SW64((uint32_t)((warpN * 64 + i * 16 + arow) * 64 + ks * 32 + koff));
            }
#pragma unroll
            for (int i = 0; i < 4; i++) LDSM4(fa[i], s0 + aoffs[i]);            // Ah
#pragma unroll
            for (int i = 0; i < 4; i++) LDSM4(fb[i], s0 + 2 * AB + boffs[i]);   // Bh
#pragma unroll
            for (int mt = 0; mt < 4; mt++)
#pragma unroll
                for (int nt = 0; nt < 8; nt++)
                    MMA16816(acc[mt][nt], fa[mt], fb[nt >> 1][nt & 1], fb[nt >> 1][(nt & 1) + 2]);
#pragma unroll
            for (int i = 0; i < 4; i++) LDSM4(f2[i], s0 + AB + aoffs[i]);       // Al
#pragma unroll
            for (int mt = 0; mt < 4; mt++)
#pragma unroll
                for (int nt = 0; nt < 8; nt++)
                    MMA16816(acc[mt][nt], f2[mt], fb[nt >> 1][nt & 1], fb[nt >> 1][(nt & 1) + 2]);
#pragma unroll
            for (int i = 0; i < 4; i++) LDSM4(fb[i], s0 + 3 * AB + boffs[i]);   // Bl (reuse)
#pragma unroll
            for (int mt = 0; mt < 4; mt++)
#pragma unroll
                for (int nt = 0; nt < 8; nt++)
                    MMA16816(acc[mt][nt], fa[mt], fb[nt >> 1][nt & 1], fb[nt >> 1][(nt & 1) + 2]);
        }
    };

    const int NC = K / KC;
    issue(0);
    CP_COMMIT();
    issue(1);
    CP_COMMIT();
    for (int c = 0; c < NC; c++) {
        if (c + 1 < NC) CP_WAIT1(); else CP_WAIT0();
        __syncthreads();                  // chunk c visible; fences compute(c-1)
        compute(c);
        if (c + 2 < NC) {
            issue(c + 2);
            CP_COMMIT();
        }
    }
    __syncthreads();                      // all compute done before smem reuse

    // ---------------- Epilogue: accum -> smem -> global ----------------
    float* esm = (float*)smem;            // [128][132] = 67.6KB < 96KB
#pragma unroll
    for (int mt = 0; mt < 4; mt++)
#pragma unroll
        for (int nt = 0; nt < 8; nt++) {
            const int r = warpM * 64 + mt * 16 + (lane >> 2);
            const int cc = warpN * 64 + nt * 8 + (lane & 3) * 2;
            *(float2*)&esm[r * 132 + cc] = make_float2(acc[mt][nt][0], acc[mt][nt][1]);
            *(float2*)&esm[(r + 8) * 132 + cc] = make_float2(acc[mt][nt][2], acc[mt][nt][3]);
        }
    __syncthreads();

    size_t zoff;
    if (cMode == 0) zoff = (size_t)z * (size_t)cBatch;
    else zoff = (size_t)(z / NHEAD) * S_LEN * HE_DIM + (size_t)(z % NHEAD) * EDIM;
    const float* bias = nullptr;
    if (biasMode == 1) bias = biasAll + (size_t)(z % NHEAD) * EDIM;
    else if (biasMode == 2) bias = biasAll;

    if (OM != 2) {
        const int m = t;                  // one row per thread
#pragma unroll
        for (int cs = 0; cs < 128; cs += 16) {
            float v[16];
#pragma unroll
            for (int j = 0; j < 16; j++) {
                v[j] = esm[m * 132 + cs + j];
                if (biasMode) v[j] += bias[col0 + cs + j];
            }
            const size_t idx = zoff + (size_t)(row0 + m) * ldc + col0 + cs;
            if (OM == 0) {
                float4* dst = (float4*)((float*)C0 + idx);
#pragma unroll
                for (int j = 0; j < 4; j++)
                    dst[j] = make_float4(v[4 * j], v[4 * j + 1], v[4 * j + 2], v[4 * j + 3]);
            } else {
                __align__(16) __nv_bfloat16 hb[16], lb[16];
#pragma unroll
                for (int j = 0; j < 16; j++) split2(v[j], hb[j], lb[j]);
                *(uint4*)((__nv_bfloat16*)C0 + idx) = *(uint4*)hb;
                *(uint4*)((__nv_bfloat16*)C0 + idx + 8) = *(uint4*)(hb + 8);
                *(uint4*)(Cl + idx) = *(uint4*)lb;
                *(uint4*)(Cl + idx + 8) = *(uint4*)(lb + 8);
            }
        }
    } else {
        const int e = t;                  // one output column (e) per thread
        const float bv = biasMode ? bias[col0 + e] : 0.0f;
#pragma unroll
        for (int m0 = 0; m0 < 128; m0 += 16) {
            __align__(16) __nv_bfloat16 hb[16], lb[16];
#pragma unroll
            for (int j = 0; j < 16; j++)
                split2(esm[(m0 + j) * 132 + e] + bv, hb[j], lb[j]);
            const size_t idx = zoff + (size_t)(col0 + e) * ldc + row0 + m0;
            *(uint4*)((__nv_bfloat16*)C0 + idx) = *(uint4*)hb;
            *(uint4*)((__nv_bfloat16*)C0 + idx + 8) = *(uint4*)(hb + 8);
            *(uint4*)(Cl + idx) = *(uint4*)lb;
            *(uint4*)(Cl + idx + 8) = *(uint4*)(lb + 8);
        }
    }
}

// ---------------------------------------------------------------------------
// Masked softmax: reads fp32 g_attn row, writes split bf16 to g_ah/g_al.
// ---------------------------------------------------------------------------
__global__ void masked_softmax_split(const void* __restrict__ mask) {
    const int z = blockIdx.x;
    const int b = z / (NHEAD * S_LEN);
    const int s = z % S_LEN;
    const float* row = g_attn + (size_t)z * S_LEN;
    __nv_bfloat16* oh = g_ah + (size_t)z * S_LEN;
    __nv_bfloat16* ol = g_al + (size_t)z * S_LEN;
    const size_t mbase = (size_t)b * S_LEN * S_LEN + (size_t)s * S_LEN;
    const int kind = g_mask_kind;
    const int tid = threadIdx.x;

    float v[8];
    float mx = -3.0e38f;
#pragma unroll
    for (int i = 0; i < 8; i++) {
        const int tt = tid + i * 256;
        bool mk;
        if (kind == 1)      mk = ((const int*)mask)[mbase + tt] != 0;
        else if (kind == 2) mk = ((const float*)mask)[mbase + tt] != 0.0f;
        else                mk = ((const unsigned char*)mask)[mbase + tt] != 0;
        const float x = mk ? row[tt] : -1.0e9f;
        v[i] = x;
        mx = fmaxf(mx, x);
    }
    __shared__ float sm[256];
    sm[tid] = mx;
    __syncthreads();
    for (int o = 128; o > 0; o >>= 1) {
        if (tid < o) sm[tid] = fmaxf(sm[tid], sm[tid + o]);
        __syncthreads();
    }
    mx = sm[0];
    __syncthreads();
    float sum = 0.0f;
#pragma unroll
    for (int i = 0; i < 8; i++) {
        v[i] = __expf(v[i] - mx);
        sum += v[i];
    }
    sm[tid] = sum;
    __syncthreads();
    for (int o = 128; o > 0; o >>= 1) {
        if (tid < o) sm[tid] += sm[tid + o];
        __syncthreads();
    }
    const float inv = 1.0f / sm[0];
#pragma unroll
    for (int i = 0; i < 8; i++) {
        __nv_bfloat16 h, l;
        split2(v[i] * inv, h, l);
        oh[tid + i * 256] = h;
        ol[tid + i * 256] = l;
    }
}

// ---------------------------------------------------------------------------
// Launcher
// ---------------------------------------------------------------------------
static void* sym(const void* s) {
    void* p = nullptr;
    cudaGetSymbolAddress(&p, s);
    return p;
}

extern "C" void kernel_launch(void* const* d_in, const int* in_sizes, int n_in,
                              void* d_out, int out_size) {
    (void)in_sizes; (void)n_in; (void)out_size;

    const float* query = (const float*)d_in[0];
    const float* key   = (const float*)d_in[1];
    const float* value = (const float*)d_in[2];
    const void*  mask  = d_in[3];
    const float* Wq = (const float*)d_in[4];
    const float* bq = (const float*)d_in[5];
    const float* Wk = (const float*)d_in[6];
    const float* bk = (const float*)d_in[7];
    const float* Wv = (const float*)d_in[8];
    const float* bv = (const float*)d_in[9];
    const float* Wo = (const float*)d_in[10];
    const float* bo = (const float*)d_in[11];
    float* out = (float*)d_out;

    typedef __nv_bfloat16 bf;
    bf* xh0 = (bf*)sym(g_xh);                       bf* xl0 = (bf*)sym(g_xl);
    bf* xh1 = xh0 + (size_t)BATCH * S_LEN * DIM;    bf* xl1 = xl0 + (size_t)BATCH * S_LEN * DIM;
    bf* xh2 = xh1 + (size_t)BATCH * S_LEN * DIM;    bf* xl2 = xl1 + (size_t)BATCH * S_LEN * DIM;
    bf* wth0 = (bf*)sym(g_wth);                     bf* wtl0 = (bf*)sym(g_wtl);
    bf* wth1 = wth0 + (size_t)NHEAD * EDIM * DIM;   bf* wtl1 = wtl0 + (size_t)NHEAD * EDIM * DIM;
    bf* wth2 = wth1 + (size_t)NHEAD * EDIM * DIM;   bf* wtl2 = wtl1 + (size_t)NHEAD * EDIM * DIM;
    bf* woth = (bf*)sym(g_woth);  bf* wotl = (bf*)sym(g_wotl);
    bf* qh = (bf*)sym(g_qh);      bf* ql = (bf*)sym(g_ql);
    bf* kh = (bf*)sym(g_kh);      bf* kl = (bf*)sym(g_kl);
    bf* vth = (bf*)sym(g_vth);    bf* vtl = (bf*)sym(g_vtl);
    float* attn = (float*)sym(g_attn);
    bf* ah = (bf*)sym(g_ah);      bf* al = (bf*)sym(g_al);
    bf* cath = (bf*)sym(g_cath);  bf* catl = (bf*)sym(g_catl);

    cudaFuncSetAttribute(mm_hmma<0>, cudaFuncAttributeMaxDynamicSharedMemorySize, SMEM_DYN);
    cudaFuncSetAttribute(mm_hmma<1>, cudaFuncAttributeMaxDynamicSharedMemorySize, SMEM_DYN);
    cudaFuncSetAttribute(mm_hmma<2>, cudaFuncAttributeMaxDynamicSharedMemorySize, SMEM_DYN);

    const int BIG = 1 << 30;

    detect_mask_kind<<<1, 1>>>(mask);

    // --- input / weight split(+transpose) prep ---
    const int nX = BATCH * S_LEN * DIM;
    split_flat<<<(nX + 255) / 256, 256>>>(query, xh0, xl0, nX);
    split_flat<<<(nX + 255) / 256, 256>>>(key,   xh1, xl1, nX);
    split_flat<<<(nX + 255) / 256, 256>>>(value, xh2, xl2, nX);
    {
        dim3 g(EDIM / 32, DIM / 32, NHEAD), bdim(32, 8);
        split_T<<<g, bdim>>>(Wq, wth0, wtl0, DIM, EDIM);
        split_T<<<g, bdim>>>(Wk, wth1, wtl1, DIM, EDIM);
        split_T<<<g, bdim>>>(Wv, wth2, wtl2, DIM, EDIM);
    }
    {
        dim3 g(EDIM / 32, HE_DIM / 32, 1), bdim(32, 8);
        split_T<<<g, bdim>>>(Wo, woth, wotl, HE_DIM, EDIM);
    }

    // --- projections: X[s,d] @ W^T[e,d]^T -> [b,h,s,e] (v transposed) ---
    {
        dim3 grid(EDIM / 128, S_LEN / TM, BATCH * NHEAD);
        mm_hmma<1><<<grid, 128, SMEM_DYN>>>(
            xh0, xl0, (long)S_LEN * DIM, NHEAD, DIM,
            wth0, wtl0, (long)EDIM * DIM, NHEAD, DIM,
            bq, 1, qh, ql, (long)S_LEN * EDIM, 0, EDIM, DIM);
        mm_hmma<1><<<grid, 128, SMEM_DYN>>>(
            xh1, xl1, (long)S_LEN * DIM, NHEAD, DIM,
            wth1, wtl1, (long)EDIM * DIM, NHEAD, DIM,
            bk, 1, kh, kl, (long)S_LEN * EDIM, 0, EDIM, DIM);
        mm_hmma<2><<<grid, 128, SMEM_DYN>>>(
            xh2, xl2, (long)S_LEN * DIM, NHEAD, DIM,
            wth2, wtl2, (long)EDIM * DIM, NHEAD, DIM,
            bv, 1, vth, vtl, (long)EDIM * S_LEN, 0, S_LEN, DIM);
    }

    // --- scores: q[s,e] @ k[t,e]^T -> fp32 attn ---
    {
        dim3 grid(S_LEN / 128, S_LEN / TM, BATCH * NHEAD);
        mm_hmma<0><<<grid, 128, SMEM_DYN>>>(
            qh, ql, (long)S_LEN * EDIM, 1, EDIM,
            kh, kl, (long)S_LEN * EDIM, BIG, EDIM,
            nullptr, 0, attn, nullptr, (long)S_LEN * S_LEN, 0, S_LEN, EDIM);
    }

    // --- masked softmax -> split bf16 ---
    masked_softmax_split<<<BATCH * NHEAD * S_LEN, 256>>>(mask);

    // --- PV: attn[s,t] @ vT[e,t]^T -> cat[b,s,h*E+e] ---
    {
        dim3 grid(EDIM / 128, S_LEN / TM, BATCH * NHEAD);
        mm_hmma<1><<<grid, 128, SMEM_DYN>>>(
            ah, al, (long)S_LEN * S_LEN, 1, S_LEN,
            vth, vtl, (long)EDIM * S_LEN, BIG, S_LEN,
            nullptr, 0, cath, catl, 0L, 1, HE_DIM, S_LEN);
    }

    // --- output projection: cat[s,he] @ WoT[e,he]^T + bo -> out fp32 ---
    {
        dim3 grid(EDIM / 128, (BATCH * S_LEN) / TM, 1);
        mm_hmma<0><<<grid, 128, SMEM_DYN>>>(
            cath, catl, 0L, 1, HE_DIM,
            woth, wotl, 0L, 1, HE_DIM,
            bo, 2, out, nullptr, 0L, 0, EDIM, HE_DIM);
    }
}

// round 12
// speedup vs baseline: 1.3485x; 1.1523x over previous
#include <cuda_runtime.h>
#include <cuda_fp16.h>
#include <cstdint>
#include <cstddef>

// Problem constants
#define S_LEN   2048
#define BATCH   2
#define DIM     512
#define NHEAD   8
#define EDIM    512
#define HE_DIM  (NHEAD * EDIM)

// GEMM tile config: CTA 128x128, 4 warps of m64n64, K-chunk 32 (64B rows, SW64)
#define TM 128
#define KC 32
#define AB 8192                       // one operand tile (hi or lo): 128*32*2
#define STG (4 * AB)                  // Ah, Al, Bh, Bl = 32768
#define SMEM_DYN (3 * STG)            // 98304 -> 2 CTAs/SM

// ---------------------------------------------------------------------------
// Scratch (device globals — no allocation allowed)
// ---------------------------------------------------------------------------
__device__ __align__(16) __half g_xh[3][BATCH * S_LEN * DIM];
__device__ __align__(16) __half g_xl[3][BATCH * S_LEN * DIM];
__device__ __align__(16) __half g_wth[3][NHEAD * EDIM * DIM];  // W^T per head
__device__ __align__(16) __half g_wtl[3][NHEAD * EDIM * DIM];
__device__ __align__(16) __half g_woth[EDIM * HE_DIM];
__device__ __align__(16) __half g_wotl[EDIM * HE_DIM];
__device__ __align__(16) __half g_qh[BATCH * NHEAD * S_LEN * EDIM];
__device__ __align__(16) __half g_ql[BATCH * NHEAD * S_LEN * EDIM];
__device__ __align__(16) __half g_kh[BATCH * NHEAD * S_LEN * EDIM];
__device__ __align__(16) __half g_kl[BATCH * NHEAD * S_LEN * EDIM];
__device__ __align__(16) __half g_vth[BATCH * NHEAD * EDIM * S_LEN]; // v^T [e,s] hi only
__device__ __align__(16) float g_attn[(size_t)BATCH * NHEAD * S_LEN * S_LEN];
__device__ __align__(16) __half g_ah[(size_t)BATCH * NHEAD * S_LEN * S_LEN];
__device__ __align__(16) __half g_al[(size_t)BATCH * NHEAD * S_LEN * S_LEN];
__device__ __align__(16) __half g_cath[BATCH * S_LEN * HE_DIM];
__device__ __align__(16) __half g_catl[BATCH * S_LEN * HE_DIM];
__device__ int g_mask_kind;

// ---------------------------------------------------------------------------
// PTX helpers (base sm_103 ISA only: cp.async, ldmatrix, mma.sync)
// ---------------------------------------------------------------------------
__device__ __forceinline__ uint32_t smem_u32(const void* p) {
    uint32_t a;
    asm("{ .reg .u64 t; cvta.to.shared.u64 t, %1; cvt.u32.u64 %0, t; }" : "=r"(a) : "l"(p));
    return a;
}
// 64B-row swizzle (Swizzle<2,4,3>): XOR bits [4:6) with bits [7:9)
#define SW64(off) ((off) ^ (((off) >> 3) & 0x30))

#define CP16(sa, gp) asm volatile( \
    "cp.async.cg.shared.global [%0], [%1], 16;" :: "r"(sa), "l"(gp) : "memory")
#define CP_COMMIT() asm volatile("cp.async.commit_group;" ::: "memory")
#define CP_WAIT1() asm volatile("cp.async.wait_group 1;" ::: "memory")
#define CP_WAIT0() asm volatile("cp.async.wait_group 0;" ::: "memory")

#define LDSM4(r, a) asm volatile( \
    "ldmatrix.sync.aligned.m8n8.x4.shared.b16 {%0,%1,%2,%3}, [%4];" \
    : "=r"((r)[0]), "=r"((r)[1]), "=r"((r)[2]), "=r"((r)[3]) : "r"(a))

#define MMA16816(d, a, b0, b1) asm volatile( \
    "mma.sync.aligned.m16n8k16.row.col.f32.f16.f16.f32 " \
    "{%0,%1,%2,%3}, {%4,%5,%6,%7}, {%8,%9}, {%0,%1,%2,%3};" \
    : "+f"((d)[0]), "+f"((d)[1]), "+f"((d)[2]), "+f"((d)[3]) \
    : "r"((a)[0]), "r"((a)[1]), "r"((a)[2]), "r"((a)[3]), "r"(b0), "r"(b1))

__device__ __forceinline__ void split2h(float v, __half& h, __half& l) {
    h = __float2half_rn(v);
    l = __float2half_rn(v - __half2float(h));
}

// ---------------------------------------------------------------------------
// Mask dtype detection (bool may arrive as u8 / i32 / f32)
// ---------------------------------------------------------------------------
__global__ void detect_mask_kind(const void* __restrict__ mask) {
    const unsigned int* w = (const unsigned int*)mask;
    bool all01 = true, allf = true;
    for (int i = 0; i < 256; i++) {
        unsigned int x = w[i];
        if (x > 1u) all01 = false;
        if (x != 0u && x != 0x3F800000u) allf = false;
    }
    g_mask_kind = all01 ? 1 : (allf ? 2 : 0);
}

// ---------------------------------------------------------------------------
// Split fp32 -> (hi, lo) fp16, flat
// ---------------------------------------------------------------------------
__global__ void split_flat(const float* __restrict__ src,
                           __half* __restrict__ hi,
                           __half* __restrict__ lo, int n) {
    int i = blockIdx.x * blockDim.x + threadIdx.x;
    if (i < n) {
        __half h, l;
        split2h(src[i], h, l);
        hi[i] = h;
        lo[i] = l;
    }
}

// ---------------------------------------------------------------------------
// Split + transpose: src [Z][R][C] fp32 -> dst [Z][C][R] fp16 hi/lo
// ---------------------------------------------------------------------------
__global__ void split_T(const float* __restrict__ src,
                        __half* __restrict__ hi,
                        __half* __restrict__ lo, int R, int C) {
    __shared__ float tile[32][33];
    const int z = blockIdx.z;
    const float* s = src + (size_t)z * R * C;
    __half* dh = hi + (size_t)z * R * C;
    __half* dl = lo + (size_t)z * R * C;
    const int c0 = blockIdx.x * 32, r0 = blockIdx.y * 32;
    const int tx = threadIdx.x, ty = threadIdx.y;
#pragma unroll
    for (int i = 0; i < 4; i++)
        tile[ty + i * 8][tx] = s[(size_t)(r0 + ty + i * 8) * C + c0 + tx];
    __syncthreads();
#pragma unroll
    for (int i = 0; i < 4; i++) {
        __half h, l;
        split2h(tile[tx][ty + i * 8], h, l);
        const size_t idx = (size_t)(c0 + ty + i * 8) * R + r0 + tx;
        dh[idx] = h;
        dl[idx] = l;
    }
}

// ---------------------------------------------------------------------------
// fp16 split HMMA GEMM: C = A @ B^T (+bias). Operands K-major as (hi,lo).
// TERMS=3: AhBh + AlBh + AhBl (dropped term ~2^-24)
// TERMS=2: AhBh + AlBh = A·Bh  (error ~2^-12; Bl never loaded)
// CTA 128x128, K-chunk 32, 3-stage cp.async pipeline, 2 CTAs/SM.
// 4 warps (128 thr), each m64 x n64: warpM = wid&1, warpN = wid>>1.
// OM: 0 = fp32 out, 1 = split-fp16 out, 2 = fp16 hi-only transposed out.
// ---------------------------------------------------------------------------
template <int OM, int TERMS>
__global__ __launch_bounds__(128, 2)
void mm_hmma(const __half* __restrict__ Ah, const __half* __restrict__ Al,
             long aBatch, int aDiv, int lda,
             const __half* __restrict__ Bh, const __half* __restrict__ Bl,
             long bBatch, int bMod, int ldb,
             const float* __restrict__ biasAll, int biasMode,
             void* __restrict__ C0, __half* __restrict__ Cl,
             long cBatch, int cMode, int ldc, int K) {
    extern __shared__ char smem[];
    const uint32_t sb = smem_u32(smem);
    const int t = threadIdx.x;
    const int lane = t & 31;
    const int wid = t >> 5;               // 0..3
    const int warpM = wid & 1;
    const int warpN = wid >> 1;
    const int z = blockIdx.z;
    const int row0 = blockIdx.y * TM;
    const int col0 = blockIdx.x * 128;

    const __half* pAh = Ah + (size_t)(z / aDiv) * (size_t)aBatch;
    const __half* pAl = Al + (size_t)(z / aDiv) * (size_t)aBatch;
    const __half* pBh = Bh + (size_t)(z % bMod) * (size_t)bBatch;
    const __half* pBl = Bl + (size_t)(z % bMod) * (size_t)bBatch;

    float acc[4][8][4] = {};              // m4-tiles x n8-tiles x frag

    auto issue = [&](int c) {
        const int k0 = c * KC;
        const uint32_t s0 = sb + (c % 3) * STG;
#pragma unroll
        for (int i = 0; i < 4; i++) {
            const int ch = t + i * 128;   // 512 16B chunks per tile
            const int r = ch >> 2;        // 0..127
            const int q = (ch & 3) * 8;
            const uint32_t so = SW64((uint32_t)(r * 64 + q * 2));
            const size_t ao = (size_t)(row0 + r) * lda + k0 + q;
            const size_t bo = (size_t)(col0 + r) * ldb + k0 + q;
            CP16(s0 + so, pAh + ao);
            CP16(s0 + AB + so, pAl + ao);
            CP16(s0 + 2 * AB + so, pBh + bo);
            if (TERMS == 3) CP16(s0 + 3 * AB + so, pBl + bo);
        }
    };

    const int arow = lane & 15;
    const int koff = (lane >> 4) * 16;    // byte offset of k half

    auto compute = [&](int c) {
        const uint32_t s0 = sb + (c % 3) * STG;
#pragma unroll
        for (int ks = 0; ks < 2; ks++) {
            uint32_t fa[4][4], f2[4][4], fb[4][4];
            uint32_t aoffs[4], boffs[4];
#pragma unroll
            for (int i = 0; i < 4; i++) {
                aoffs[i] = SW64((uint32_t)((warpM * 64 + i * 16 + arow) * 64 + ks * 32 + koff));
                boffs[i] = SW64((uint32_t)((warpN * 64 + i * 16 + arow) * 64 + ks * 32 + koff));
            }
#pragma unroll
            for (int i = 0; i < 4; i++) LDSM4(fa[i], s0 + aoffs[i]);            // Ah
#pragma unroll
            for (int i = 0; i < 4; i++) LDSM4(fb[i], s0 + 2 * AB + boffs[i]);   // Bh
#pragma unroll
            for (int mt = 0; mt < 4; mt++)
#pragma unroll
                for (int nt = 0; nt < 8; nt++)
                    MMA16816(acc[mt][nt], fa[mt], fb[nt >> 1][nt & 1], fb[nt >> 1][(nt & 1) + 2]);
#pragma unroll
            for (int i = 0; i < 4; i++) LDSM4(f2[i], s0 + AB + aoffs[i]);       // Al
#pragma unroll
            for (int mt = 0; mt < 4; mt++)
#pragma unroll
                for (int nt = 0; nt < 8; nt++)
                    MMA16816(acc[mt][nt], f2[mt], fb[nt >> 1][nt & 1], fb[nt >> 1][(nt & 1) + 2]);
            if (TERMS == 3) {
#pragma unroll
                for (int i = 0; i < 4; i++) LDSM4(fb[i], s0 + 3 * AB + boffs[i]);  // Bl
#pragma unroll
                for (int mt = 0; mt < 4; mt++)
#pragma unroll
                    for (int nt = 0; nt < 8; nt++)
                        MMA16816(acc[mt][nt], fa[mt], fb[nt >> 1][nt & 1], fb[nt >> 1][(nt & 1) + 2]);
            }
        }
    };

    const int NC = K / KC;
    issue(0);
    CP_COMMIT();
    issue(1);
    CP_COMMIT();
    for (int c = 0; c < NC; c++) {
        if (c + 1 < NC) CP_WAIT1(); else CP_WAIT0();
        __syncthreads();                  // chunk c visible; fences compute(c-1)
        compute(c);
        if (c + 2 < NC) {
            issue(c + 2);
            CP_COMMIT();
        }
    }
    __syncthreads();                      // all compute done before smem reuse

    // ---------------- Epilogue: accum -> smem -> global ----------------
    float* esm = (float*)smem;            // [128][132] = 67.6KB < 96KB
#pragma unroll
    for (int mt = 0; mt < 4; mt++)
#pragma unroll
        for (int nt = 0; nt < 8; nt++) {
            const int r = warpM * 64 + mt * 16 + (lane >> 2);
            const int cc = warpN * 64 + nt * 8 + (lane & 3) * 2;
            *(float2*)&esm[r * 132 + cc] = make_float2(acc[mt][nt][0], acc[mt][nt][1]);
            *(float2*)&esm[(r + 8) * 132 + cc] = make_float2(acc[mt][nt][2], acc[mt][nt][3]);
        }
    __syncthreads();

    size_t zoff;
    if (cMode == 0) zoff = (size_t)z * (size_t)cBatch;
    else zoff = (size_t)(z / NHEAD) * S_LEN * HE_DIM + (size_t)(z % NHEAD) * EDIM;
    const float* bias = nullptr;
    if (biasMode == 1) bias = biasAll + (size_t)(z % NHEAD) * EDIM;
    else if (biasMode == 2) bias = biasAll;

    if (OM != 2) {
        const int m = t;                  // one row per thread
#pragma unroll
        for (int cs = 0; cs < 128; cs += 16) {
            float v[16];
#pragma unroll
            for (int j = 0; j < 16; j++) {
                v[j] = esm[m * 132 + cs + j];
                if (biasMode) v[j] += bias[col0 + cs + j];
            }
            const size_t idx = zoff + (size_t)(row0 + m) * ldc + col0 + cs;
            if (OM == 0) {
                float4* dst = (float4*)((float*)C0 + idx);
#pragma unroll
                for (int j = 0; j < 4; j++)
                    dst[j] = make_float4(v[4 * j], v[4 * j + 1], v[4 * j + 2], v[4 * j + 3]);
            } else {
                __align__(16) __half hb[16], lb[16];
#pragma unroll
                for (int j = 0; j < 16; j++) split2h(v[j], hb[j], lb[j]);
                *(uint4*)((__half*)C0 + idx) = *(uint4*)hb;
                *(uint4*)((__half*)C0 + idx + 8) = *(uint4*)(hb + 8);
                *(uint4*)(Cl + idx) = *(uint4*)lb;
                *(uint4*)(Cl + idx + 8) = *(uint4*)(lb + 8);
            }
        }
    } else {
        const int e = t;                  // one output column (e) per thread; hi only
        const float bv = biasMode ? bias[col0 + e] : 0.0f;
#pragma unroll
        for (int m0 = 0; m0 < 128; m0 += 16) {
            __align__(16) __half hb[16];
#pragma unroll
            for (int j = 0; j < 16; j++)
                hb[j] = __float2half_rn(esm[(m0 + j) * 132 + e] + bv);
            const size_t idx = zoff + (size_t)(col0 + e) * ldc + row0 + m0;
            *(uint4*)((__half*)C0 + idx) = *(uint4*)hb;
            *(uint4*)((__half*)C0 + idx + 8) = *(uint4*)(hb + 8);
        }
    }
}

// ---------------------------------------------------------------------------
// Masked softmax: reads fp32 g_attn row, writes split fp16 to g_ah/g_al.
// ---------------------------------------------------------------------------
__global__ void masked_softmax_split(const void* __restrict__ mask) {
    const int z = blockIdx.x;
    const int b = z / (NHEAD * S_LEN);
    const int s = z % S_LEN;
    const float* row = g_attn + (size_t)z * S_LEN;
    __half* oh = g_ah + (size_t)z * S_LEN;
    __half* ol = g_al + (size_t)z * S_LEN;
    const size_t mbase = (size_t)b * S_LEN * S_LEN + (size_t)s * S_LEN;
    const int kind = g_mask_kind;
    const int tid = threadIdx.x;

    float v[8];
    float mx = -3.0e38f;
#pragma unroll
    for (int i = 0; i < 8; i++) {
        const int tt = tid + i * 256;
        bool mk;
        if (kind == 1)      mk = ((const int*)mask)[mbase + tt] != 0;
        else if (kind == 2) mk = ((const float*)mask)[mbase + tt] != 0.0f;
        else                mk = ((const unsigned char*)mask)[mbase + tt] != 0;
        const float x = mk ? row[tt] : -1.0e9f;
        v[i] = x;
        mx = fmaxf(mx, x);
    }
    __shared__ float sm[256];
    sm[tid] = mx;
    __syncthreads();
    for (int o = 128; o > 0; o >>= 1) {
        if (tid < o) sm[tid] = fmaxf(sm[tid], sm[tid + o]);
        __syncthreads();
    }
    mx = sm[0];
    __syncthreads();
    float sum = 0.0f;
#pragma unroll
    for (int i = 0; i < 8; i++) {
        v[i] = __expf(v[i] - mx);
        sum += v[i];
    }
    sm[tid] = sum;
    __syncthreads();
    for (int o = 128; o > 0; o >>= 1) {
        if (tid < o) sm[tid] += sm[tid + o];
        __syncthreads();
    }
    const float inv = 1.0f / sm[0];
#pragma unroll
    for (int i = 0; i < 8; i++) {
        __half h, l;
        split2h(v[i] * inv, h, l);
        oh[tid + i * 256] = h;
        ol[tid + i * 256] = l;
    }
}

// ---------------------------------------------------------------------------
// Launcher
// ---------------------------------------------------------------------------
static void* sym(const void* s) {
    void* p = nullptr;
    cudaGetSymbolAddress(&p, s);
    return p;
}

extern "C" void kernel_launch(void* const* d_in, const int* in_sizes, int n_in,
                              void* d_out, int out_size) {
    (void)in_sizes; (void)n_in; (void)out_size;

    const float* query = (const float*)d_in[0];
    const float* key   = (const float*)d_in[1];
    const float* value = (const float*)d_in[2];
    const void*  mask  = d_in[3];
    const float* Wq = (const float*)d_in[4];
    const float* bq = (const float*)d_in[5];
    const float* Wk = (const float*)d_in[6];
    const float* bk = (const float*)d_in[7];
    const float* Wv = (const float*)d_in[8];
    const float* bv = (const float*)d_in[9];
    const float* Wo = (const float*)d_in[10];
    const float* bo = (const float*)d_in[11];
    float* out = (float*)d_out;

    typedef __half hf;
    hf* xh0 = (hf*)sym(g_xh);                       hf* xl0 = (hf*)sym(g_xl);
    hf* xh1 = xh0 + (size_t)BATCH * S_LEN * DIM;    hf* xl1 = xl0 + (size_t)BATCH * S_LEN * DIM;
    hf* xh2 = xh1 + (size_t)BATCH * S_LEN * DIM;    hf* xl2 = xl1 + (size_t)BATCH * S_LEN * DIM;
    hf* wth0 = (hf*)sym(g_wth);                     hf* wtl0 = (hf*)sym(g_wtl);
    hf* wth1 = wth0 + (size_t)NHEAD * EDIM * DIM;   hf* wtl1 = wtl0 + (size_t)NHEAD * EDIM * DIM;
    hf* wth2 = wth1 + (size_t)NHEAD * EDIM * DIM;   hf* wtl2 = wtl1 + (size_t)NHEAD * EDIM * DIM;
    hf* woth = (hf*)sym(g_woth);  hf* wotl = (hf*)sym(g_wotl);
    hf* qh = (hf*)sym(g_qh);      hf* ql = (hf*)sym(g_ql);
    hf* kh = (hf*)sym(g_kh);      hf* kl = (hf*)sym(g_kl);
    hf* vth = (hf*)sym(g_vth);
    float* attn = (float*)sym(g_attn);
    hf* ah = (hf*)sym(g_ah);      hf* al = (hf*)sym(g_al);
    hf* cath = (hf*)sym(g_cath);  hf* catl = (hf*)sym(g_catl);

    cudaFuncSetAttribute(mm_hmma<0, 3>, cudaFuncAttributeMaxDynamicSharedMemorySize, SMEM_DYN);
    cudaFuncSetAttribute(mm_hmma<1, 3>, cudaFuncAttributeMaxDynamicSharedMemorySize, SMEM_DYN);
    cudaFuncSetAttribute(mm_hmma<2, 2>, cudaFuncAttributeMaxDynamicSharedMemorySize, SMEM_DYN);
    cudaFuncSetAttribute(mm_hmma<1, 2>, cudaFuncAttributeMaxDynamicSharedMemorySize, SMEM_DYN);
    cudaFuncSetAttribute(mm_hmma<0, 2>, cudaFuncAttributeMaxDynamicSharedMemorySize, SMEM_DYN);

    const int BIG = 1 << 30;

    detect_mask_kind<<<1, 1>>>(mask);

    // --- input / weight split(+transpose) prep ---
    const int nX = BATCH * S_LEN * DIM;
    split_flat<<<(nX + 255) / 256, 256>>>(query, xh0, xl0, nX);
    split_flat<<<(nX + 255) / 256, 256>>>(key,   xh1, xl1, nX);
    split_flat<<<(nX + 255) / 256, 256>>>(value, xh2, xl2, nX);
    {
        dim3 g(EDIM / 32, DIM / 32, NHEAD), bdim(32, 8);
        split_T<<<g, bdim>>>(Wq, wth0, wtl0, DIM, EDIM);
        split_T<<<g, bdim>>>(Wk, wth1, wtl1, DIM, EDIM);
        split_T<<<g, bdim>>>(Wv, wth2, wtl2, DIM, EDIM);
    }
    {
        dim3 g(EDIM / 32, HE_DIM / 32, 1), bdim(32, 8);
        split_T<<<g, bdim>>>(Wo, woth, wotl, HE_DIM, EDIM);
    }

    // --- projections: X[s,d] @ W^T[e,d]^T -> [b,h,s,e] (v transposed, hi only) ---
    {
        dim3 grid(EDIM / 128, S_LEN / TM, BATCH * NHEAD);
        mm_hmma<1, 3><<<grid, 128, SMEM_DYN>>>(
            xh0, xl0, (long)S_LEN * DIM, NHEAD, DIM,
            wth0, wtl0, (long)EDIM * DIM, NHEAD, DIM,
            bq, 1, qh, ql, (long)S_LEN * EDIM, 0, EDIM, DIM);
        mm_hmma<1, 3><<<grid, 128, SMEM_DYN>>>(
            xh1, xl1, (long)S_LEN * DIM, NHEAD, DIM,
            wth1, wtl1, (long)EDIM * DIM, NHEAD, DIM,
            bk, 1, kh, kl, (long)S_LEN * EDIM, 0, EDIM, DIM);
        mm_hmma<2, 2><<<grid, 128, SMEM_DYN>>>(
            xh2, xl2, (long)S_LEN * DIM, NHEAD, DIM,
            wth2, wtl2, (long)EDIM * DIM, NHEAD, DIM,
            bv, 1, vth, nullptr, (long)EDIM * S_LEN, 0, S_LEN, DIM);
    }

    // --- scores: q[s,e] @ k[t,e]^T -> fp32 attn (3-term fp16) ---
    {
        dim3 grid(S_LEN / 128, S_LEN / TM, BATCH * NHEAD);
        mm_hmma<0, 3><<<grid, 128, SMEM_DYN>>>(
            qh, ql, (long)S_LEN * EDIM, 1, EDIM,
            kh, kl, (long)S_LEN * EDIM, BIG, EDIM,
            nullptr, 0, attn, nullptr, (long)S_LEN * S_LEN, 0, S_LEN, EDIM);
    }

    // --- masked softmax -> split fp16 ---
    masked_softmax_split<<<BATCH * NHEAD * S_LEN, 256>>>(mask);

    // --- PV: attn(full) @ vT_hi^T -> cat[b,s,h*E+e] (2-term) ---
    {
        dim3 grid(EDIM / 128, S_LEN / TM, BATCH * NHEAD);
        mm_hmma<1, 2><<<grid, 128, SMEM_DYN>>>(
            ah, al, (long)S_LEN * S_LEN, 1, S_LEN,
            vth, vth, (long)EDIM * S_LEN, BIG, S_LEN,
            nullptr, 0, cath, catl, 0L, 1, HE_DIM, S_LEN);
    }

    // --- output projection: cat(full) @ WoT_hi^T + bo -> out fp32 (2-term) ---
    {
        dim3 grid(EDIM / 128, (BATCH * S_LEN) / TM, 1);
        mm_hmma<0, 2><<<grid, 128, SMEM_DYN>>>(
            cath, catl, 0L, 1, HE_DIM,
            woth, woth, 0L, 1, HE_DIM,
            bo, 2, out, nullptr, 0L, 0, EDIM, HE_DIM);
    }
}

// round 14
// speedup vs baseline: 1.6364x; 1.2136x over previous
#include <cuda_runtime.h>
#include <cuda_fp16.h>
#include <cstdint>
#include <cstddef>

// Problem constants
#define S_LEN   2048
#define BATCH   2
#define DIM     512
#define NHEAD   8
#define EDIM    512
#define HE_DIM  (NHEAD * EDIM)

// GEMM tile config: CTA 128x128, 4 warps of m64n64, K-chunk 32 (64B rows, SW64)
#define TM 128
#define KC 32
#define AB 8192                       // one operand tile (hi or lo): 128*32*2
#define STG (4 * AB)                  // Ah, Al, Bh, Bl slots = 32768
#define SMEM_DYN (3 * STG)            // 98304 -> 2 CTAs/SM

// ---------------------------------------------------------------------------
// Scratch (device globals — no allocation allowed)
// ---------------------------------------------------------------------------
__device__ __align__(16) __half g_xh[3][BATCH * S_LEN * DIM];
__device__ __align__(16) __half g_xl[3][BATCH * S_LEN * DIM];
__device__ __align__(16) __half g_wth[3][NHEAD * EDIM * DIM];  // W^T per head
__device__ __align__(16) __half g_wtl[3][NHEAD * EDIM * DIM];
__device__ __align__(16) __half g_woth[EDIM * HE_DIM];
__device__ __align__(16) __half g_wotl[EDIM * HE_DIM];
__device__ __align__(16) __half g_qh[BATCH * NHEAD * S_LEN * EDIM];
__device__ __align__(16) __half g_ql[BATCH * NHEAD * S_LEN * EDIM];
__device__ __align__(16) __half g_kh[BATCH * NHEAD * S_LEN * EDIM];
__device__ __align__(16) __half g_kl[BATCH * NHEAD * S_LEN * EDIM];
__device__ __align__(16) __half g_vth[BATCH * NHEAD * EDIM * S_LEN]; // v^T [e,s] hi only
__device__ __align__(16) float g_attn[(size_t)BATCH * NHEAD * S_LEN * S_LEN];
__device__ __align__(16) __half g_ah[(size_t)BATCH * NHEAD * S_LEN * S_LEN];
__device__ __align__(16) __half g_cath[BATCH * S_LEN * HE_DIM];
__device__ int g_mask_kind;

// ---------------------------------------------------------------------------
// PTX helpers (base sm_103 ISA only: cp.async, ldmatrix, mma.sync)
// ---------------------------------------------------------------------------
__device__ __forceinline__ uint32_t smem_u32(const void* p) {
    uint32_t a;
    asm("{ .reg .u64 t; cvta.to.shared.u64 t, %1; cvt.u32.u64 %0, t; }" : "=r"(a) : "l"(p));
    return a;
}
// 64B-row swizzle (Swizzle<2,4,3>): XOR bits [4:6) with bits [7:9)
#define SW64(off) ((off) ^ (((off) >> 3) & 0x30))

#define CP16(sa, gp) asm volatile( \
    "cp.async.cg.shared.global [%0], [%1], 16;" :: "r"(sa), "l"(gp) : "memory")
#define CP_COMMIT() asm volatile("cp.async.commit_group;" ::: "memory")
#define CP_WAIT1() asm volatile("cp.async.wait_group 1;" ::: "memory")
#define CP_WAIT0() asm volatile("cp.async.wait_group 0;" ::: "memory")

#define LDSM4(r, a) asm volatile( \
    "ldmatrix.sync.aligned.m8n8.x4.shared.b16 {%0,%1,%2,%3}, [%4];" \
    : "=r"((r)[0]), "=r"((r)[1]), "=r"((r)[2]), "=r"((r)[3]) : "r"(a))

#define MMA16816(d, a, b0, b1) asm volatile( \
    "mma.sync.aligned.m16n8k16.row.col.f32.f16.f16.f32 " \
    "{%0,%1,%2,%3}, {%4,%5,%6,%7}, {%8,%9}, {%0,%1,%2,%3};" \
    : "+f"((d)[0]), "+f"((d)[1]), "+f"((d)[2]), "+f"((d)[3]) \
    : "r"((a)[0]), "r"((a)[1]), "r"((a)[2]), "r"((a)[3]), "r"(b0), "r"(b1))

__device__ __forceinline__ void split2h(float v, __half& h, __half& l) {
    h = __float2half_rn(v);
    l = __float2half_rn(v - __half2float(h));
}

// ---------------------------------------------------------------------------
// Mask dtype detection (bool may arrive as u8 / i32 / f32)
// ---------------------------------------------------------------------------
__global__ void detect_mask_kind(const void* __restrict__ mask) {
    const unsigned int* w = (const unsigned int*)mask;
    bool all01 = true, allf = true;
    for (int i = 0; i < 256; i++) {
        unsigned int x = w[i];
        if (x > 1u) all01 = false;
        if (x != 0u && x != 0x3F800000u) allf = false;
    }
    g_mask_kind = all01 ? 1 : (allf ? 2 : 0);
}

// ---------------------------------------------------------------------------
// Split fp32 -> (hi, lo) fp16, flat
// ---------------------------------------------------------------------------
__global__ void split_flat(const float* __restrict__ src,
                           __half* __restrict__ hi,
                           __half* __restrict__ lo, int n) {
    int i = blockIdx.x * blockDim.x + threadIdx.x;
    if (i < n) {
        __half h, l;
        split2h(src[i], h, l);
        hi[i] = h;
        lo[i] = l;
    }
}

// ---------------------------------------------------------------------------
// Split + transpose: src [Z][R][C] fp32 -> dst [Z][C][R] fp16 hi/lo
// ---------------------------------------------------------------------------
__global__ void split_T(const float* __restrict__ src,
                        __half* __restrict__ hi,
                        __half* __restrict__ lo, int R, int C) {
    __shared__ float tile[32][33];
    const int z = blockIdx.z;
    const float* s = src + (size_t)z * R * C;
    __half* dh = hi + (size_t)z * R * C;
    __half* dl = lo + (size_t)z * R * C;
    const int c0 = blockIdx.x * 32, r0 = blockIdx.y * 32;
    const int tx = threadIdx.x, ty = threadIdx.y;
#pragma unroll
    for (int i = 0; i < 4; i++)
        tile[ty + i * 8][tx] = s[(size_t)(r0 + ty + i * 8) * C + c0 + tx];
    __syncthreads();
#pragma unroll
    for (int i = 0; i < 4; i++) {
        __half h, l;
        split2h(tile[tx][ty + i * 8], h, l);
        const size_t idx = (size_t)(c0 + ty + i * 8) * R + r0 + tx;
        dh[idx] = h;
        dl[idx] = l;
    }
}

// ---------------------------------------------------------------------------
// fp16 split HMMA GEMM: C = A @ B^T (+bias). Operands K-major as (hi,lo).
// TERMS=3: AhBh + AlBh + AhBl  (err ~2^-22)
// TERMS=2: AhBh + AlBh         (err ~u|B|)
// TERMS=1: AhBh                (err ~u(|A|+|B|))
// CTA 128x128, K-chunk 32, 3-stage cp.async pipeline, 2 CTAs/SM.
// 4 warps (128 thr), each m64 x n64: warpM = wid&1, warpN = wid>>1.
// OM: 0 fp32 out, 1 split-fp16 out, 2 fp16 hi transposed, 3 fp16 hi out.
// ---------------------------------------------------------------------------
template <int OM, int TERMS>
__global__ __launch_bounds__(128, 2)
void mm_hmma(const __half* __restrict__ Ah, const __half* __restrict__ Al,
             long aBatch, int aDiv, int lda,
             const __half* __restrict__ Bh, const __half* __restrict__ Bl,
             long bBatch, int bMod, int ldb,
             const float* __restrict__ biasAll, int biasMode,
             void* __restrict__ C0, __half* __restrict__ Cl,
             long cBatch, int cMode, int ldc, int K) {
    extern __shared__ char smem[];
    const uint32_t sb = smem_u32(smem);
    const int t = threadIdx.x;
    const int lane = t & 31;
    const int wid = t >> 5;               // 0..3
    const int warpM = wid & 1;
    const int warpN = wid >> 1;
    const int z = blockIdx.z;
    const int row0 = blockIdx.y * TM;
    const int col0 = blockIdx.x * 128;

    const __half* pAh = Ah + (size_t)(z / aDiv) * (size_t)aBatch;
    const __half* pAl = Al + (size_t)(z / aDiv) * (size_t)aBatch;
    const __half* pBh = Bh + (size_t)(z % bMod) * (size_t)bBatch;
    const __half* pBl = Bl + (size_t)(z % bMod) * (size_t)bBatch;

    float acc[4][8][4] = {};              // m4-tiles x n8-tiles x frag

    auto issue = [&](int c) {
        const int k0 = c * KC;
        const uint32_t s0 = sb + (c % 3) * STG;
#pragma unroll
        for (int i = 0; i < 4; i++) {
            const int ch = t + i * 128;   // 512 16B chunks per tile
            const int r = ch >> 2;        // 0..127
            const int q = (ch & 3) * 8;
            const uint32_t so = SW64((uint32_t)(r * 64 + q * 2));
            const size_t ao = (size_t)(row0 + r) * lda + k0 + q;
            const size_t bo = (size_t)(col0 + r) * ldb + k0 + q;
            CP16(s0 + so, pAh + ao);
            if (TERMS >= 2) CP16(s0 + AB + so, pAl + ao);
            CP16(s0 + 2 * AB + so, pBh + bo);
            if (TERMS == 3) CP16(s0 + 3 * AB + so, pBl + bo);
        }
    };

    const int arow = lane & 15;
    const int koff = (lane >> 4) * 16;    // byte offset of k half

    auto compute = [&](int c) {
        const uint32_t s0 = sb + (c % 3) * STG;
#pragma unroll
        for (int ks = 0; ks < 2; ks++) {
            uint32_t fa[4][4], f2[4][4], fb[4][4];
            uint32_t aoffs[4], boffs[4];
#pragma unroll
            for (int i = 0; i < 4; i++) {
                aoffs[i] = SW64((uint32_t)((warpM * 64 + i * 16 + arow) * 64 + ks * 32 + koff));
                boffs[i] = SW64((uint32_t)((warpN * 64 + i * 16 + arow) * 64 + ks * 32 + koff));
            }
#pragma unroll
            for (int i = 0; i < 4; i++) LDSM4(fa[i], s0 + aoffs[i]);            // Ah
#pragma unroll
            for (int i = 0; i < 4; i++) LDSM4(fb[i], s0 + 2 * AB + boffs[i]);   // Bh
#pragma unroll
            for (int mt = 0; mt < 4; mt++)
#pragma unroll
                for (int nt = 0; nt < 8; nt++)
                    MMA16816(acc[mt][nt], fa[mt], fb[nt >> 1][nt & 1], fb[nt >> 1][(nt & 1) + 2]);
            if (TERMS >= 2) {
#pragma unroll
                for (int i = 0; i < 4; i++) LDSM4(f2[i], s0 + AB + aoffs[i]);   // Al
#pragma unroll
                for (int mt = 0; mt < 4; mt++)
#pragma unroll
                    for (int nt = 0; nt < 8; nt++)
                        MMA16816(acc[mt][nt], f2[mt], fb[nt >> 1][nt & 1], fb[nt >> 1][(nt & 1) + 2]);
            }
            if (TERMS == 3) {
#pragma unroll
                for (int i = 0; i < 4; i++) LDSM4(fb[i], s0 + 3 * AB + boffs[i]);  // Bl
#pragma unroll
                for (int mt = 0; mt < 4; mt++)
#pragma unroll
                    for (int nt = 0; nt < 8; nt++)
                        MMA16816(acc[mt][nt], fa[mt], fb[nt >> 1][nt & 1], fb[nt >> 1][(nt & 1) + 2]);
            }
        }
    };

    const int NC = K / KC;
    issue(0);
    CP_COMMIT();
    issue(1);
    CP_COMMIT();
    for (int c = 0; c < NC; c++) {
        if (c + 1 < NC) CP_WAIT1(); else CP_WAIT0();
        __syncthreads();                  // chunk c visible; fences compute(c-1)
        compute(c);
        if (c + 2 < NC) {
            issue(c + 2);
            CP_COMMIT();
        }
    }
    __syncthreads();                      // all compute done before smem reuse

    // ---------------- Epilogue: accum -> smem -> global ----------------
    float* esm = (float*)smem;            // [128][132] = 67.6KB < 96KB
#pragma unroll
    for (int mt = 0; mt < 4; mt++)
#pragma unroll
        for (int nt = 0; nt < 8; nt++) {
            const int r = warpM * 64 + mt * 16 + (lane >> 2);
            const int cc = warpN * 64 + nt * 8 + (lane & 3) * 2;
            *(float2*)&esm[r * 132 + cc] = make_float2(acc[mt][nt][0], acc[mt][nt][1]);
            *(float2*)&esm[(r + 8) * 132 + cc] = make_float2(acc[mt][nt][2], acc[mt][nt][3]);
        }
    __syncthreads();

    size_t zoff;
    if (cMode == 0) zoff = (size_t)z * (size_t)cBatch;
    else zoff = (size_t)(z / NHEAD) * S_LEN * HE_DIM + (size_t)(z % NHEAD) * EDIM;
    const float* bias = nullptr;
    if (biasMode == 1) bias = biasAll + (size_t)(z % NHEAD) * EDIM;
    else if (biasMode == 2) bias = biasAll;

    if (OM != 2) {
        const int m = t;                  // one row per thread
#pragma unroll
        for (int cs = 0; cs < 128; cs += 16) {
            float v[16];
#pragma unroll
            for (int j = 0; j < 16; j++) {
                v[j] = esm[m * 132 + cs + j];
                if (biasMode) v[j] += bias[col0 + cs + j];
            }
            const size_t idx = zoff + (size_t)(row0 + m) * ldc + col0 + cs;
            if (OM == 0) {
                float4* dst = (float4*)((float*)C0 + idx);
#pragma unroll
                for (int j = 0; j < 4; j++)
                    dst[j] = make_float4(v[4 * j], v[4 * j + 1], v[4 * j + 2], v[4 * j + 3]);
            } else if (OM == 1) {
                __align__(16) __half hb[16], lb[16];
#pragma unroll
                for (int j = 0; j < 16; j++) split2h(v[j], hb[j], lb[j]);
                *(uint4*)((__half*)C0 + idx) = *(uint4*)hb;
                *(uint4*)((__half*)C0 + idx + 8) = *(uint4*)(hb + 8);
                *(uint4*)(Cl + idx) = *(uint4*)lb;
                *(uint4*)(Cl + idx + 8) = *(uint4*)(lb + 8);
            } else {                      // OM == 3: fp16 hi only
                __align__(16) __half hb[16];
#pragma unroll
                for (int j = 0; j < 16; j++) hb[j] = __float2half_rn(v[j]);
                *(uint4*)((__half*)C0 + idx) = *(uint4*)hb;
                *(uint4*)((__half*)C0 + idx + 8) = *(uint4*)(hb + 8);
            }
        }
    } else {
        const int e = t;                  // one output column (e) per thread; hi only
        const float bv = biasMode ? bias[col0 + e] : 0.0f;
#pragma unroll
        for (int m0 = 0; m0 < 128; m0 += 16) {
            __align__(16) __half hb[16];
#pragma unroll
            for (int j = 0; j < 16; j++)
                hb[j] = __float2half_rn(esm[(m0 + j) * 132 + e] + bv);
            const size_t idx = zoff + (size_t)(col0 + e) * ldc + row0 + m0;
            *(uint4*)((__half*)C0 + idx) = *(uint4*)hb;
            *(uint4*)((__half*)C0 + idx + 8) = *(uint4*)(hb + 8);
        }
    }
}

// ---------------------------------------------------------------------------
// Masked softmax: one block per (b, s) row, serving all 8 heads.
// Mask row read ONCE (saves 7/8 of mask traffic); writes fp16 hi only.
// ---------------------------------------------------------------------------
__global__ void masked_softmax8(const void* __restrict__ mask) {
    const int z = blockIdx.x;             // b * S_LEN + s
    const int b = z / S_LEN;
    const int s = z % S_LEN;
    const size_t mbase = (size_t)b * S_LEN * S_LEN + (size_t)s * S_LEN;
    const int kind = g_mask_kind;
    const int tid = threadIdx.x;

    // Load mask row once -> additive bias in registers
    float mb[8];
#pragma unroll
    for (int i = 0; i < 8; i++) {
        const int tt = tid + i * 256;
        bool mk;
        if (kind == 1)      mk = ((const int*)mask)[mbase + tt] != 0;
        else if (kind == 2) mk = ((const float*)mask)[mbase + tt] != 0.0f;
        else                mk = ((const unsigned char*)mask)[mbase + tt] != 0;
        mb[i] = mk ? 0.0f : -1.0e9f;
    }

    __shared__ float sm[256];
    for (int h = 0; h < NHEAD; h++) {
        const size_t roff = ((size_t)(b * NHEAD + h) * S_LEN + s) * S_LEN;
        const float* row = g_attn + roff;
        __half* oh = g_ah + roff;

        float v[8];
        float mx = -3.0e38f;
#pragma unroll
        for (int i = 0; i < 8; i++) {
            const float x = row[tid + i * 256] + mb[i];
            v[i] = x;
            mx = fmaxf(mx, x);
        }
        sm[tid] = mx;
        __syncthreads();
        for (int o = 128; o > 0; o >>= 1) {
            if (tid < o) sm[tid] = fmaxf(sm[tid], sm[tid + o]);
            __syncthreads();
        }
        mx = sm[0];
        __syncthreads();
        float sum = 0.0f;
#pragma unroll
        for (int i = 0; i < 8; i++) {
            v[i] = __expf(v[i] - mx);
            sum += v[i];
        }
        sm[tid] = sum;
        __syncthreads();
        for (int o = 128; o > 0; o >>= 1) {
            if (tid < o) sm[tid] += sm[tid + o];
            __syncthreads();
        }
        const float inv = 1.0f / sm[0];
#pragma unroll
        for (int i = 0; i < 8; i++)
            oh[tid + i * 256] = __float2half_rn(v[i] * inv);
        __syncthreads();                  // sm reuse next head
    }
}

// ---------------------------------------------------------------------------
// Launcher
// ---------------------------------------------------------------------------
static void* sym(const void* s) {
    void* p = nullptr;
    cudaGetSymbolAddress(&p, s);
    return p;
}

extern "C" void kernel_launch(void* const* d_in, const int* in_sizes, int n_in,
                              void* d_out, int out_size) {
    (void)in_sizes; (void)n_in; (void)out_size;

    const float* query = (const float*)d_in[0];
    const float* key   = (const float*)d_in[1];
    const float* value = (const float*)d_in[2];
    const void*  mask  = d_in[3];
    const float* Wq = (const float*)d_in[4];
    const float* bq = (const float*)d_in[5];
    const float* Wk = (const float*)d_in[6];
    const float* bk = (const float*)d_in[7];
    const float* Wv = (const float*)d_in[8];
    const float* bv = (const float*)d_in[9];
    const float* Wo = (const float*)d_in[10];
    const float* bo = (const float*)d_in[11];
    float* out = (float*)d_out;

    typedef __half hf;
    hf* xh0 = (hf*)sym(g_xh);                       hf* xl0 = (hf*)sym(g_xl);
    hf* xh1 = xh0 + (size_t)BATCH * S_LEN * DIM;    hf* xl1 = xl0 + (size_t)BATCH * S_LEN * DIM;
    hf* xh2 = xh1 + (size_t)BATCH * S_LEN * DIM;    hf* xl2 = xl1 + (size_t)BATCH * S_LEN * DIM;
    hf* wth0 = (hf*)sym(g_wth);                     hf* wtl0 = (hf*)sym(g_wtl);
    hf* wth1 = wth0 + (size_t)NHEAD * EDIM * DIM;   hf* wtl1 = wtl0 + (size_t)NHEAD * EDIM * DIM;
    hf* wth2 = wth1 + (size_t)NHEAD * EDIM * DIM;   hf* wtl2 = wtl1 + (size_t)NHEAD * EDIM * DIM;
    hf* woth = (hf*)sym(g_woth);  hf* wotl = (hf*)sym(g_wotl);
    hf* qh = (hf*)sym(g_qh);      hf* ql = (hf*)sym(g_ql);
    hf* kh = (hf*)sym(g_kh);      hf* kl = (hf*)sym(g_kl);
    hf* vth = (hf*)sym(g_vth);
    float* attn = (float*)sym(g_attn);
    hf* ah = (hf*)sym(g_ah);
    hf* cath = (hf*)sym(g_cath);

    cudaFuncSetAttribute(mm_hmma<1, 3>, cudaFuncAttributeMaxDynamicSharedMemorySize, SMEM_DYN);
    cudaFuncSetAttribute(mm_hmma<0, 3>, cudaFuncAttributeMaxDynamicSharedMemorySize, SMEM_DYN);
    cudaFuncSetAttribute(mm_hmma<2, 1>, cudaFuncAttributeMaxDynamicSharedMemorySize, SMEM_DYN);
    cudaFuncSetAttribute(mm_hmma<3, 1>, cudaFuncAttributeMaxDynamicSharedMemorySize, SMEM_DYN);
    cudaFuncSetAttribute(mm_hmma<0, 1>, cudaFuncAttributeMaxDynamicSharedMemorySize, SMEM_DYN);

    const int BIG = 1 << 30;

    detect_mask_kind<<<1, 1>>>(mask);

    // --- input / weight split(+transpose) prep ---
    const int nX = BATCH * S_LEN * DIM;
    split_flat<<<(nX + 255) / 256, 256>>>(query, xh0, xl0, nX);
    split_flat<<<(nX + 255) / 256, 256>>>(key,   xh1, xl1, nX);
    split_flat<<<(nX + 255) / 256, 256>>>(value, xh2, xl2, nX);
    {
        dim3 g(EDIM / 32, DIM / 32, NHEAD), bdim(32, 8);
        split_T<<<g, bdim>>>(Wq, wth0, wtl0, DIM, EDIM);
        split_T<<<g, bdim>>>(Wk, wth1, wtl1, DIM, EDIM);
        split_T<<<g, bdim>>>(Wv, wth2, wtl2, DIM, EDIM);
    }
    {
        dim3 g(EDIM / 32, HE_DIM / 32, 1), bdim(32, 8);
        split_T<<<g, bdim>>>(Wo, woth, wotl, HE_DIM, EDIM);
    }

    // --- projections: q/k 3-term split-fp16 out; v 1-term, hi-only transposed ---
    {
        dim3 grid(EDIM / 128, S_LEN / TM, BATCH * NHEAD);
        mm_hmma<1, 3><<<grid, 128, SMEM_DYN>>>(
            xh0, xl0, (long)S_LEN * DIM, NHEAD, DIM,
            wth0, wtl0, (long)EDIM * DIM, NHEAD, DIM,
            bq, 1, qh, ql, (long)S_LEN * EDIM, 0, EDIM, DIM);
        mm_hmma<1, 3><<<grid, 128, SMEM_DYN>>>(
            xh1, xl1, (long)S_LEN * DIM, NHEAD, DIM,
            wth1, wtl1, (long)EDIM * DIM, NHEAD, DIM,
            bk, 1, kh, kl, (long)S_LEN * EDIM, 0, EDIM, DIM);
        mm_hmma<2, 1><<<grid, 128, SMEM_DYN>>>(
            xh2, xh2, (long)S_LEN * DIM, NHEAD, DIM,
            wth2, wth2, (long)EDIM * DIM, NHEAD, DIM,
            bv, 1, vth, nullptr, (long)EDIM * S_LEN, 0, S_LEN, DIM);
    }

    // --- scores: q[s,e] @ k[t,e]^T -> fp32 attn (3-term fp16) ---
    {
        dim3 grid(S_LEN / 128, S_LEN / TM, BATCH * NHEAD);
        mm_hmma<0, 3><<<grid, 128, SMEM_DYN>>>(
            qh, ql, (long)S_LEN * EDIM, 1, EDIM,
            kh, kl, (long)S_LEN * EDIM, BIG, EDIM,
            nullptr, 0, attn, nullptr, (long)S_LEN * S_LEN, 0, S_LEN, EDIM);
    }

    // --- masked softmax (8 heads per block) -> fp16 hi ---
    masked_softmax8<<<BATCH * S_LEN, 256>>>(mask);

    // --- PV: ah @ vT_hi^T -> cat fp16 hi (1-term) ---
    {
        dim3 grid(EDIM / 128, S_LEN / TM, BATCH * NHEAD);
        mm_hmma<3, 1><<<grid, 128, SMEM_DYN>>>(
            ah, ah, (long)S_LEN * S_LEN, 1, S_LEN,
            vth, vth, (long)EDIM * S_LEN, BIG, S_LEN,
            nullptr, 0, cath, nullptr, 0L, 1, HE_DIM, S_LEN);
    }

    // --- output projection: cath @ WoT_hi^T + bo -> out fp32 (1-term) ---
    {
        dim3 grid(EDIM / 128, (BATCH * S_LEN) / TM, 1);
        mm_hmma<0, 1><<<grid, 128, SMEM_DYN>>>(
            cath, cath, 0L, 1, HE_DIM,
            woth, woth, 0L, 1, HE_DIM,
            bo, 2, out, nullptr, 0L, 0, EDIM, HE_DIM);
    }
}